// round 1
// baseline (speedup 1.0000x reference)
#include <cuda_runtime.h>
#include <cuda_bf16.h>

// Problem constants (from reference): P=8, N=16, WS=32, H=W=512.
#define PP    8
#define NSLOT 16
#define WSZ   32
#define HDIM  512
#define WDIM  512
#define MAXM  625   // (32-8+1)^2

__global__ __launch_bounds__(256, 1)
void patches_kernel(const float* __restrict__ g_re,
                    const float* __restrict__ g_im,
                    const int*   __restrict__ p_refx,
                    const int*   __restrict__ p_refy,
                    float*       __restrict__ out)
{
    __shared__ float wr[WSZ][WSZ + 1];
    __shared__ float wi[WSZ][WSZ + 1];
    __shared__ float dists[MAXM];
    __shared__ int   sel[NSLOT];

    const int bc  = blockIdx.x;
    const int tid = threadIdx.x;

    const int ref_x = *p_refx;
    const int ref_y = *p_refy;

    int wx0 = ref_x - WSZ / 2; if (wx0 < 0) wx0 = 0;
    int wx1 = ref_x + WSZ / 2; if (wx1 > HDIM) wx1 = HDIM;
    int wy0 = ref_y - WSZ / 2; if (wy0 < 0) wy0 = 0;
    int wy1 = ref_y + WSZ / 2; if (wy1 > WDIM) wy1 = WDIM;

    const int Wh = wx1 - wx0;
    const int Ww = wy1 - wy0;
    const int Ph = Wh - PP + 1;
    const int Pw = Ww - PP + 1;
    const int M  = Ph * Pw;

    const size_t base = (size_t)bc * HDIM * WDIM;

    // ---- Stage window into SMEM (coalesced rows of 32 floats) ----
    for (int t = tid; t < Wh * Ww; t += 256) {
        const int r = t / Ww;
        const int c = t - r * Ww;
        const size_t gidx = base + (size_t)(wx0 + r) * WDIM + (wy0 + c);
        wr[r][c] = g_re[gidx];
        wi[r][c] = g_im[gidx];
    }
    __syncthreads();

    const int rx = ref_x - wx0;
    const int ry = ref_y - wy0;

    // ---- Distances: each thread handles strided patches.
    // Ref loads broadcast across the warp; window loads are consecutive
    // columns across consecutive lanes -> conflict-free.
    for (int m = tid; m < M; m += 256) {
        const int px = m / Pw;
        const int py = m - px * Pw;
        float s = 0.0f;
        #pragma unroll
        for (int i = 0; i < PP; i++) {
            #pragma unroll
            for (int j = 0; j < PP; j++) {
                const float dr = wr[px + i][py + j] - wr[rx + i][ry + j];
                const float dm = wi[px + i][py + j] - wi[rx + i][ry + j];
                s += dr * dr;
                s += dm * dm;
            }
        }
        // 0.5 * mean over p*p*2 = 128 elements  -> s / 256
        dists[m] = s * (1.0f / 256.0f);
    }
    __syncthreads();

    // ---- Serial selection scan (exact replay of reference semantics).
    // Invariant: slot array stays sorted ascending; each new value overwrites
    // the first slot holding a larger value. Lane l (<16) owns slot l.
    if (tid < 32) {
        float nd  = 1e33f;
        int   idx = -1;
        for (int m = 0; m < M; m++) {
            const float di = dists[m];
            unsigned mask = __ballot_sync(0xffffffffu, (tid < NSLOT) && (nd > di));
            mask &= 0xffffu;
            if (mask) {
                const int j = __ffs(mask) - 1;
                if (tid == j) { nd = di; idx = m; }
            }
        }
        if (tid < NSLOT) sel[tid] = idx;
    }
    __syncthreads();

    // ---- Gather winning patches, write 2048 coalesced floats per CTA.
    // out layout: [bc][slot][k=i*8+j][comp], comp fastest.
    for (int t = tid; t < NSLOT * PP * PP * 2; t += 256) {
        const int comp = t & 1;
        const int k    = (t >> 1) & (PP * PP - 1);
        const int s    = t >> 7;
        const int m    = sel[s];
        float v = 0.0f;  // unfilled slot -> zeros (matches reference init)
        if (m >= 0) {
            const int px = m / Pw;
            const int py = m - px * Pw;
            const int i  = k >> 3;
            const int j  = k & 7;
            v = comp ? wi[px + i][py + j] : wr[px + i][py + j];
        }
        out[(size_t)bc * (NSLOT * PP * PP * 2) + t] = v;
    }
}

extern "C" void kernel_launch(void* const* d_in, const int* in_sizes, int n_in,
                              void* d_out, int out_size)
{
    const float* g_re  = (const float*)d_in[0];
    const float* g_im  = (const float*)d_in[1];
    const int*   refx  = (const int*)d_in[2];
    const int*   refy  = (const int*)d_in[3];
    float*       out   = (float*)d_out;

    const int BC = in_sizes[0] / (HDIM * WDIM);   // 96
    patches_kernel<<<BC, 256>>>(g_re, g_im, refx, refy, out);
}